// round 11
// baseline (speedup 1.0000x reference)
#include <cuda_runtime.h>
#include <cuda_bf16.h>
#include <math.h>

#define B_  16
#define T_  512
#define C_  256
#define H_  8
#define HST 32
#define HSS 64

#define N_BTC (B_*T_*C_)
#define N_FF  (B_*T_*4*C_)
#define N_SCS ((long long)B_*H_*C_*C_)

#define O_h    0
#define O_q    (O_h    + N_BTC)
#define O_k    (O_q    + N_BTC)
#define O_v    (O_k    + N_BTC)
#define O_o    (O_v    + N_BTC)
#define O_x    (O_o    + N_BTC)
#define O_h2   (O_x    + N_BTC)
#define O_tout (O_h2   + N_BTC)
#define O_hs   (O_tout + N_BTC)
#define O_qs   (O_hs   + N_BTC)
#define O_ks   (O_qs   + N_BTC)
#define O_x2   (O_ks   + N_BTC)
#define O_h3   (O_x2   + N_BTC)
#define O_ff   (O_h3   + N_BTC)
#define O_scS  (O_ff   + N_FF)
#define TOTAL_SCRATCH (O_scS + N_SCS)

__device__ float g_buf[TOTAL_SCRATCH];

// ============================== LayerNorm ==================================
__global__ void ln_kernel(const float* __restrict__ x, float* __restrict__ y,
                          const float* __restrict__ w, const float* __restrict__ b,
                          int L) {
    long long base = (long long)blockIdx.x * L;
    int tid = threadIdx.x;
    float s = 0.f, s2 = 0.f;
    for (int i = tid; i < L; i += 256) {
        float v = x[base + i];
        s += v; s2 += v * v;
    }
    __shared__ float sh[64];
    #pragma unroll
    for (int o = 16; o > 0; o >>= 1) {
        s  += __shfl_down_sync(0xffffffffu, s,  o);
        s2 += __shfl_down_sync(0xffffffffu, s2, o);
    }
    int warp = tid >> 5, lane = tid & 31;
    if (lane == 0) { sh[warp] = s; sh[warp + 32] = s2; }
    __syncthreads();
    if (tid == 0) {
        float ts = 0.f, ts2 = 0.f;
        for (int i = 0; i < 8; i++) { ts += sh[i]; ts2 += sh[32 + i]; }
        float m = ts / (float)L;
        float var = ts2 / (float)L - m * m;
        sh[0] = m;
        sh[1] = rsqrtf(var + 1e-6f);
    }
    __syncthreads();
    float m = sh[0], r = sh[1];
    for (int i = tid; i < L; i += 256)
        y[base + i] = (x[base + i] - m) * r * w[i] + b[i];
}

// ===================== Softmax (full row, length L<=512) ===================
__global__ void softmax_kernel(float* __restrict__ x, int L) {
    long long base = (long long)blockIdx.x * L;
    int tid = threadIdx.x;
    float v[2];
    #pragma unroll
    for (int c = 0; c < 2; c++) {
        int i = tid + c * 256;
        v[c] = (i < L) ? x[base + i] : -3.4e38f;
    }
    float mx = fmaxf(v[0], v[1]);
    __shared__ float sh[32];
    #pragma unroll
    for (int o = 16; o > 0; o >>= 1) mx = fmaxf(mx, __shfl_down_sync(0xffffffffu, mx, o));
    int warp = tid >> 5, lane = tid & 31;
    if (lane == 0) sh[warp] = mx;
    __syncthreads();
    if (tid == 0) {
        float m = sh[0];
        for (int i = 1; i < 8; i++) m = fmaxf(m, sh[i]);
        sh[0] = m;
    }
    __syncthreads();
    mx = sh[0];
    float sum = 0.f;
    #pragma unroll
    for (int c = 0; c < 2; c++) {
        int i = tid + c * 256;
        if (i < L) { v[c] = expf(v[c] - mx); sum += v[c]; }
    }
    __syncthreads();
    #pragma unroll
    for (int o = 16; o > 0; o >>= 1) sum += __shfl_down_sync(0xffffffffu, sum, o);
    if (lane == 0) sh[warp] = sum;
    __syncthreads();
    if (tid == 0) {
        float s = 0.f;
        for (int i = 0; i < 8; i++) s += sh[i];
        sh[0] = 1.f / s;
    }
    __syncthreads();
    float inv = sh[0];
    #pragma unroll
    for (int c = 0; c < 2; c++) {
        int i = tid + c * 256;
        if (i < L) x[base + i] = v[c] * inv;
    }
}

// ============================ Mean over heads ==============================
__global__ void mean_heads_kernel(const float* __restrict__ sc, float* __restrict__ out) {
    long long idx = (long long)blockIdx.x * 256 + threadIdx.x;
    const long long NN = (long long)B_ * C_ * C_;
    if (idx >= NN) return;
    long long b = idx / (C_ * C_);
    long long r = idx % (C_ * C_);
    float s = 0.f;
    #pragma unroll
    for (int h = 0; h < H_; h++)
        s += sc[(b * H_ + h) * (long long)(C_ * C_) + r];
    out[idx] = s * 0.125f;
}

// ======================== shared MMA helpers ===============================
__device__ __forceinline__ void split2(float x0, float x1, unsigned &hi, unsigned &lo) {
    __nv_bfloat162 h = __floats2bfloat162_rn(x0, x1);
    float r0 = x0 - __bfloat162float(h.x);
    float r1 = x1 - __bfloat162float(h.y);
    __nv_bfloat162 l = __floats2bfloat162_rn(r0, r1);
    hi = *reinterpret_cast<unsigned*>(&h);
    lo = *reinterpret_cast<unsigned*>(&l);
}
__device__ __forceinline__ void mma16(float* c, const unsigned* a, const unsigned* b) {
    asm volatile("mma.sync.aligned.m16n8k16.row.col.f32.bf16.bf16.f32 "
        "{%0,%1,%2,%3}, {%4,%5,%6,%7}, {%8,%9}, {%0,%1,%2,%3};"
        : "+f"(c[0]), "+f"(c[1]), "+f"(c[2]), "+f"(c[3])
        : "r"(a[0]), "r"(a[1]), "r"(a[2]), "r"(a[3]), "r"(b[0]), "r"(b[1]));
}
__device__ __forceinline__ int SWZ(int kp, int c) { return c ^ (((kp >> 1) & 7) << 2); }

// ==================== Fused causal flash attention =========================
// grid: (8 row tiles, B*H). block 256 (warps: wm=wid&3 rows, wn=wid>>2 col-half)
// q,k,v fp32 [B,T,C] head slice at h*32. ob fp32 [B,T,C].
#define ATT_BMP 136
#define ATT_VP  33
// smem words (unsigned/float):
#define ATT_QH 0
#define ATT_QL (ATT_QH + 16*ATT_BMP)
#define ATT_KH (ATT_QL + 16*ATT_BMP)
#define ATT_KL (ATT_KH + 16*ATT_BMP)
#define ATT_VH (ATT_KL + 16*ATT_BMP)
#define ATT_VL (ATT_VH + 64*ATT_VP)
#define ATT_OS (ATT_VL + 64*ATT_VP)
#define ATT_ML (ATT_OS + 2*128*33)
#define ATT_TOT (ATT_ML + 2*128*2)
#define ATT_SMEM (ATT_TOT * 4)

__global__ __launch_bounds__(256, 1)
void fused_attn(const float* __restrict__ q, const float* __restrict__ k,
                const float* __restrict__ v, float* __restrict__ ob) {
    extern __shared__ unsigned sm[];
    float* smf = reinterpret_cast<float*>(sm);

    int rt = blockIdx.x;                 // row tile
    int bh = blockIdx.y;
    int b = bh / H_, hh = bh % H_;
    int row0 = rt * 128;
    const long long TC = (long long)T_ * C_;
    const float* qp = q + (long long)b * TC + hh * 32;
    const float* kp_ = k + (long long)b * TC + hh * 32;
    const float* vp = v + (long long)b * TC + hh * 32;

    int tid = threadIdx.x, lane = tid & 31, wid = tid >> 5;
    int wm = wid & 3, wn = wid >> 2;
    int r = lane >> 2, cq = lane & 3;

    // ---- load + split q tile into QH/QL (R5 A-pattern) ----
    {
        unsigned* ah = sm + ATT_QH;
        unsigned* al = sm + ATT_QL;
        #pragma unroll
        for (int i = 0; i < 4; i++) {
            int idx = tid + i * 256;
            int m = idx >> 3, k4 = idx & 7;
            float4 vq = *reinterpret_cast<const float4*>(qp + (long long)(row0 + m) * C_ + k4 * 4);
            int mc = m ^ (k4 << 2);
            unsigned h0, l0, h1, l1;
            split2(vq.x, vq.y, h0, l0);
            split2(vq.z, vq.w, h1, l1);
            ah[(k4 * 2) * ATT_BMP + mc] = h0;     al[(k4 * 2) * ATT_BMP + mc] = l0;
            ah[(k4 * 2 + 1) * ATT_BMP + mc] = h1; al[(k4 * 2 + 1) * ATT_BMP + mc] = l1;
        }
    }

    float oacc[2][4][4];
    #pragma unroll
    for (int im = 0; im < 2; im++)
        #pragma unroll
        for (int nj = 0; nj < 4; nj++)
            #pragma unroll
            for (int e = 0; e < 4; e++) oacc[im][nj][e] = 0.f;
    float mrow[2][2], lrow[2][2];
    #pragma unroll
    for (int im = 0; im < 2; im++)
        #pragma unroll
        for (int hf = 0; hf < 2; hf++) { mrow[im][hf] = -1e30f; lrow[im][hf] = 0.f; }

    const float scale = 0.1767766952966369f;

    for (int kb = 0; kb <= rt; kb++) {
        int ks0 = kb * 128;
        __syncthreads();   // prior block's mma reads done before overwrite
        // ---- load + split k tile ----
        {
            unsigned* ah = sm + ATT_KH;
            unsigned* al = sm + ATT_KL;
            #pragma unroll
            for (int i = 0; i < 4; i++) {
                int idx = tid + i * 256;
                int m = idx >> 3, k4 = idx & 7;
                float4 vk = *reinterpret_cast<const float4*>(kp_ + (long long)(ks0 + m) * C_ + k4 * 4);
                int mc = m ^ (k4 << 2);
                unsigned h0, l0, h1, l1;
                split2(vk.x, vk.y, h0, l0);
                split2(vk.z, vk.w, h1, l1);
                ah[(k4 * 2) * ATT_BMP + mc] = h0;     al[(k4 * 2) * ATT_BMP + mc] = l0;
                ah[(k4 * 2 + 1) * ATT_BMP + mc] = h1; al[(k4 * 2 + 1) * ATT_BMP + mc] = l1;
            }
        }
        // ---- load + split v tile (pairs over s) ----
        {
            unsigned* vh = sm + ATT_VH;
            unsigned* vl = sm + ATT_VL;
            #pragma unroll
            for (int i = 0; i < 8; i++) {
                int pidx = tid + i * 256;
                int kk2 = pidx >> 5, d = pidx & 31;
                const float* bp = vp + (long long)(ks0 + kk2 * 2) * C_ + d;
                float b0 = bp[0], b1 = bp[C_];
                unsigned h0, l0;
                split2(b0, b1, h0, l0);
                vh[kk2 * ATT_VP + d] = h0;
                vl[kk2 * ATT_VP + d] = l0;
            }
        }
        __syncthreads();

        // ---- scores: 128x128 tile, warp slice 32 x 64 ----
        float p[2][8][4];
        #pragma unroll
        for (int im = 0; im < 2; im++)
            #pragma unroll
            for (int j = 0; j < 8; j++)
                #pragma unroll
                for (int e = 0; e < 4; e++) p[im][j][e] = 0.f;

        const unsigned* qh = sm + ATT_QH;
        const unsigned* ql = sm + ATT_QL;
        const unsigned* kh = sm + ATT_KH;
        const unsigned* kl = sm + ATT_KL;
        #pragma unroll
        for (int k16 = 0; k16 < 2; k16++) {
            int kp0 = k16 * 8 + cq, kp1 = kp0 + 4;
            unsigned bf_h[8][2], bf_l[8][2];
            #pragma unroll
            for (int j = 0; j < 8; j++) {
                int ncol = wn * 64 + j * 8 + r;
                bf_h[j][0] = kh[kp0 * ATT_BMP + SWZ(kp0, ncol)];
                bf_h[j][1] = kh[kp1 * ATT_BMP + SWZ(kp1, ncol)];
                bf_l[j][0] = kl[kp0 * ATT_BMP + SWZ(kp0, ncol)];
                bf_l[j][1] = kl[kp1 * ATT_BMP + SWZ(kp1, ncol)];
            }
            #pragma unroll
            for (int im = 0; im < 2; im++) {
                int mr = wm * 32 + im * 16 + r;
                unsigned afh[4], afl[4];
                afh[0] = qh[kp0 * ATT_BMP + SWZ(kp0, mr)];
                afh[1] = qh[kp0 * ATT_BMP + SWZ(kp0, mr + 8)];
                afh[2] = qh[kp1 * ATT_BMP + SWZ(kp1, mr)];
                afh[3] = qh[kp1 * ATT_BMP + SWZ(kp1, mr + 8)];
                afl[0] = ql[kp0 * ATT_BMP + SWZ(kp0, mr)];
                afl[1] = ql[kp0 * ATT_BMP + SWZ(kp0, mr + 8)];
                afl[2] = ql[kp1 * ATT_BMP + SWZ(kp1, mr)];
                afl[3] = ql[kp1 * ATT_BMP + SWZ(kp1, mr + 8)];
                #pragma unroll
                for (int j = 0; j < 8; j++) {
                    mma16(p[im][j], afl, bf_h[j]);
                    mma16(p[im][j], afh, bf_l[j]);
                    mma16(p[im][j], afh, bf_h[j]);
                }
            }
        }

        bool diag = (kb == rt);
        // scale + mask (mask for max via -1e30)
        #pragma unroll
        for (int im = 0; im < 2; im++)
            #pragma unroll
            for (int j = 0; j < 8; j++)
                #pragma unroll
                for (int e = 0; e < 4; e++) {
                    float s = p[im][j][e] * scale;
                    if (diag) {
                        int rw = row0 + wm * 32 + im * 16 + r + (e >> 1) * 8;
                        int cl = ks0 + wn * 64 + j * 8 + 2 * cq + (e & 1);
                        if (cl > rw) s = -1e30f;
                    }
                    p[im][j][e] = s;
                }

        // ---- online softmax ----
        #pragma unroll
        for (int im = 0; im < 2; im++) {
            #pragma unroll
            for (int hf = 0; hf < 2; hf++) {
                float bm = -1e30f;
                #pragma unroll
                for (int j = 0; j < 8; j++)
                    bm = fmaxf(bm, fmaxf(p[im][j][hf * 2], p[im][j][hf * 2 + 1]));
                bm = fmaxf(bm, __shfl_xor_sync(0xffffffffu, bm, 1));
                bm = fmaxf(bm, __shfl_xor_sync(0xffffffffu, bm, 2));
                float mn = fmaxf(mrow[im][hf], bm);
                float alpha = expf(mrow[im][hf] - mn);
                float rs = 0.f;
                #pragma unroll
                for (int j = 0; j < 8; j++) {
                    #pragma unroll
                    for (int q2 = 0; q2 < 2; q2++) {
                        int e = hf * 2 + q2;
                        float pv = expf(p[im][j][e] - mn);
                        if (diag) {
                            int rw = row0 + wm * 32 + im * 16 + r + hf * 8;
                            int cl = ks0 + wn * 64 + j * 8 + 2 * cq + q2;
                            if (cl > rw) pv = 0.f;
                        }
                        p[im][j][e] = pv;
                        rs += pv;
                    }
                }
                rs += __shfl_xor_sync(0xffffffffu, rs, 1);
                rs += __shfl_xor_sync(0xffffffffu, rs, 2);
                lrow[im][hf] = lrow[im][hf] * alpha + rs;
                mrow[im][hf] = mn;
                // rescale o rows for this (im,hf)
                #pragma unroll
                for (int nj = 0; nj < 4; nj++) {
                    oacc[im][nj][hf * 2]     *= alpha;
                    oacc[im][nj][hf * 2 + 1] *= alpha;
                }
            }
        }

        // ---- P @ V ----
        const unsigned* vh = sm + ATT_VH;
        const unsigned* vl = sm + ATT_VL;
        #pragma unroll
        for (int kc = 0; kc < 4; kc++) {
            // V b-frags for this k16 chunk (s = wn*64 + kc*16 + ...)
            int kpA = (wn * 32) + kc * 8 + cq;     // kpair index into 64 pairs
            int kpB = kpA + 4;
            unsigned bvh[4][2], bvl[4][2];
            #pragma unroll
            for (int nj = 0; nj < 4; nj++) {
                int dc = nj * 8 + r;
                bvh[nj][0] = vh[kpA * ATT_VP + dc];
                bvh[nj][1] = vh[kpB * ATT_VP + dc];
                bvl[nj][0] = vl[kpA * ATT_VP + dc];
                bvl[nj][1] = vl[kpB * ATT_VP + dc];
            }
            #pragma unroll
            for (int im = 0; im < 2; im++) {
                int j0 = 2 * kc, j1 = 2 * kc + 1;
                unsigned pah[4], pal[4];
                split2(p[im][j0][0], p[im][j0][1], pah[0], pal[0]);
                split2(p[im][j0][2], p[im][j0][3], pah[1], pal[1]);
                split2(p[im][j1][0], p[im][j1][1], pah[2], pal[2]);
                split2(p[im][j1][2], p[im][j1][3], pah[3], pal[3]);
                #pragma unroll
                for (int nj = 0; nj < 4; nj++) {
                    mma16(oacc[im][nj], pal, bvh[nj]);
                    mma16(oacc[im][nj], pah, bvl[nj]);
                    mma16(oacc[im][nj], pah, bvh[nj]);
                }
            }
        }
    }

    // ---- merge the two wn halves & write ----
    __syncthreads();
    float* os = smf + ATT_OS;
    float* ml = smf + ATT_ML;
    #pragma unroll
    for (int im = 0; im < 2; im++)
        #pragma unroll
        for (int nj = 0; nj < 4; nj++)
            #pragma unroll
            for (int e = 0; e < 4; e++) {
                int rl = wm * 32 + im * 16 + r + (e >> 1) * 8;
                int cl = nj * 8 + 2 * cq + (e & 1);
                os[(wn * 128 + rl) * 33 + cl] = oacc[im][nj][e];
            }
    if (cq == 0) {
        #pragma unroll
        for (int im = 0; im < 2; im++)
            #pragma unroll
            for (int hf = 0; hf < 2; hf++) {
                int rl = wm * 32 + im * 16 + r + hf * 8;
                ml[(wn * 128 + rl) * 2]     = mrow[im][hf];
                ml[(wn * 128 + rl) * 2 + 1] = lrow[im][hf];
            }
    }
    __syncthreads();
    float* obp = ob + (long long)blockIdx.y / H_ * 0;  // (unused; recompute below)
    for (int idx = tid; idx < 128 * 32; idx += 256) {
        int rl = idx >> 5, d = idx & 31;
        float m0 = ml[rl * 2], l0 = ml[rl * 2 + 1];
        float m1 = ml[(128 + rl) * 2], l1 = ml[(128 + rl) * 2 + 1];
        float mm = fmaxf(m0, m1);
        float w0 = expf(m0 - mm), w1 = expf(m1 - mm);
        float denom = l0 * w0 + l1 * w1;
        float val = (os[rl * 33 + d] * w0 + os[(128 + rl) * 33 + d] * w1) / denom;
        ob[(long long)b * TC + (long long)(row0 + rl) * C_ + hh * 32 + d] = val;
    }
    (void)obp;
}

// ================= Pipelined tensor-core GEMM (3x BF16) ====================
#define FLAG_RELU    1
#define FLAG_NT      4

template<int BN, int WN>
__global__ __launch_bounds__(128 * WN)
void mma_gemm(const float* __restrict__ A, int lda, long long sAo, long long sAi, int nInner,
              const float* __restrict__ Bm, int ldb, long long sBo, long long sBi,
              float* __restrict__ Cm, int ldc, long long sCo, long long sCi,
              int K, float alpha,
              const float* __restrict__ bias,
              const float* __restrict__ res, int ldres, long long sRo, long long sRi,
              int flags) {
    constexpr int BM = 128, BK = 32;
    constexpr int THREADS = 128 * WN;
    constexpr int WNT = BN / WN;
    constexpr int NJ  = WNT / 8;
    constexpr int BMP = BM + 8, BNP = BN + 8;
    constexpr int AH_O = 0;
    constexpr int AL_O = 16 * BMP;
    constexpr int BH_O = 32 * BMP;
    constexpr int BL_O = 32 * BMP + 16 * BNP;
    constexpr int STG  = 32 * (BMP + BNP);
    constexpr int AITER = (BM * 8) / THREADS;
    constexpr int BITER = (BN * 8) / THREADS;

    extern __shared__ unsigned sm[];

    int z  = blockIdx.z;
    int zo = z / nInner, zi = z % nInner;
    const float* Ab = A  + zo * sAo + zi * sAi;
    const float* Bb = Bm + zo * sBo + zi * sBi;
    float*       Cb = Cm + zo * sCo + zi * sCi;
    const float* Rb = res ? (res + zo * sRo + zi * sRi) : (const float*)0;

    int tid = threadIdx.x, lane = tid & 31, wid = tid >> 5;
    int wm = wid & 3, wn = wid >> 2;
    int row0 = blockIdx.y * BM;
    int col0 = blockIdx.x * BN;
    int r = lane >> 2, cq = lane & 3;
    bool nt = (flags & FLAG_NT) != 0;

    int nk = K / BK;

    float4 ra[AITER], rb[BITER];

    auto loadT = [&](int k0) {
        #pragma unroll
        for (int i = 0; i < AITER; i++) {
            int idx = tid + i * THREADS;
            int m = idx >> 3, k4 = idx & 7;
            ra[i] = *reinterpret_cast<const float4*>(
                Ab + (long long)(row0 + m) * lda + k0 + k4 * 4);
        }
        if (nt) {
            #pragma unroll
            for (int i = 0; i < BITER; i++) {
                int idx = tid + i * THREADS;
                int n = idx >> 3, k4 = idx & 7;
                rb[i] = *reinterpret_cast<const float4*>(
                    Bb + (long long)(col0 + n) * ldb + k0 + k4 * 4);
            }
        } else {
            #pragma unroll
            for (int i = 0; i < BITER; i++) {
                #pragma unroll
                for (int pz = 0; pz < 2; pz++) {
                    int pidx = tid + (i * 2 + pz) * THREADS;
                    int kk2 = pidx / BN;
                    int n = pidx % BN;
                    const float* bp = Bb + (long long)(k0 + kk2 * 2) * ldb + col0 + n;
                    float b0 = bp[0], b1 = bp[ldb];
                    if (pz == 0) { rb[i].x = b0; rb[i].y = b1; }
                    else         { rb[i].z = b0; rb[i].w = b1; }
                }
            }
        }
    };

    auto storeT = [&](int s) {
        unsigned* ah = sm + s * STG + AH_O;
        unsigned* al = sm + s * STG + AL_O;
        unsigned* bh = sm + s * STG + BH_O;
        unsigned* bl = sm + s * STG + BL_O;
        #pragma unroll
        for (int i = 0; i < AITER; i++) {
            int idx = tid + i * THREADS;
            int m = idx >> 3, k4 = idx & 7;
            int mc = m ^ (k4 << 2);
            unsigned h0, l0, h1, l1;
            split2(ra[i].x, ra[i].y, h0, l0);
            split2(ra[i].z, ra[i].w, h1, l1);
            ah[(k4 * 2) * BMP + mc] = h0;     al[(k4 * 2) * BMP + mc] = l0;
            ah[(k4 * 2 + 1) * BMP + mc] = h1; al[(k4 * 2 + 1) * BMP + mc] = l1;
        }
        if (nt) {
            #pragma unroll
            for (int i = 0; i < BITER; i++) {
                int idx = tid + i * THREADS;
                int n = idx >> 3, k4 = idx & 7;
                int nc = n ^ (k4 << 2);
                unsigned h0, l0, h1, l1;
                split2(rb[i].x, rb[i].y, h0, l0);
                split2(rb[i].z, rb[i].w, h1, l1);
                bh[(k4 * 2) * BNP + nc] = h0;     bl[(k4 * 2) * BNP + nc] = l0;
                bh[(k4 * 2 + 1) * BNP + nc] = h1; bl[(k4 * 2 + 1) * BNP + nc] = l1;
            }
        } else {
            #pragma unroll
            for (int i = 0; i < BITER; i++) {
                #pragma unroll
                for (int pz = 0; pz < 2; pz++) {
                    int pidx = tid + (i * 2 + pz) * THREADS;
                    int kk2 = pidx / BN;
                    int n = pidx % BN;
                    int nc = SWZ(kk2, n);
                    float b0 = pz ? rb[i].z : rb[i].x;
                    float b1 = pz ? rb[i].w : rb[i].y;
                    unsigned h0, l0;
                    split2(b0, b1, h0, l0);
                    bh[kk2 * BNP + nc] = h0;
                    bl[kk2 * BNP + nc] = l0;
                }
            }
        }
    };

    float acc[2][NJ][4];
    #pragma unroll
    for (int i = 0; i < 2; i++)
        #pragma unroll
        for (int j = 0; j < NJ; j++)
            #pragma unroll
            for (int e = 0; e < 4; e++) acc[i][j][e] = 0.f;

    auto compute = [&](int s) {
        const unsigned* ah = sm + s * STG + AH_O;
        const unsigned* al = sm + s * STG + AL_O;
        const unsigned* bhp = sm + s * STG + BH_O;
        const unsigned* blp = sm + s * STG + BL_O;
        #pragma unroll
        for (int k16 = 0; k16 < 2; k16++) {
            int kp0 = k16 * 8 + cq, kp1 = kp0 + 4;
            unsigned bf_h[NJ][2], bf_l[NJ][2];
            #pragma unroll
            for (int j = 0; j < NJ; j++) {
                int ncol = wn * WNT + j * 8 + r;
                bf_h[j][0] = bhp[kp0 * BNP + SWZ(kp0, ncol)];
                bf_h[j][1] = bhp[kp1 * BNP + SWZ(kp1, ncol)];
                bf_l[j][0] = blp[kp0 * BNP + SWZ(kp0, ncol)];
                bf_l[j][1] = blp[kp1 * BNP + SWZ(kp1, ncol)];
            }
            #pragma unroll
            for (int im = 0; im < 2; im++) {
                int mrow = wm * 32 + im * 16 + r;
                unsigned afh[4], afl[4];
                afh[0] = ah[kp0 * BMP + SWZ(kp0, mrow)];
                afh[1] = ah[kp0 * BMP + SWZ(kp0, mrow + 8)];
                afh[2] = ah[kp1 * BMP + SWZ(kp1, mrow)];
                afh[3] = ah[kp1 * BMP + SWZ(kp1, mrow + 8)];
                afl[0] = al[kp0 * BMP + SWZ(kp0, mrow)];
                afl[1] = al[kp0 * BMP + SWZ(kp0, mrow + 8)];
                afl[2] = al[kp1 * BMP + SWZ(kp1, mrow)];
                afl[3] = al[kp1 * BMP + SWZ(kp1, mrow + 8)];
                #pragma unroll
                for (int j = 0; j < NJ; j++) {
                    mma16(acc[im][j], afl, bf_h[j]);
                    mma16(acc[im][j], afh, bf_l[j]);
                    mma16(acc[im][j], afh, bf_h[j]);
                }
            }
        }
    };

    loadT(0);
    storeT(0);
    int p = 0;
    for (int kb = 0; kb < nk; kb++) {
        __syncthreads();
        bool more = (kb + 1) < nk;
        if (more) loadT((kb + 1) * BK);
        compute(p);
        if (more) storeT(1 - p);
        p ^= 1;
    }

    #pragma unroll
    for (int im = 0; im < 2; im++) {
        #pragma unroll
        for (int j = 0; j < NJ; j++) {
            int gm0 = row0 + wm * 32 + im * 16 + r;
            int gn  = col0 + wn * WNT + j * 8 + cq * 2;
            #pragma unroll
            for (int half = 0; half < 2; half++) {
                int gm = gm0 + half * 8;
                float v0 = acc[im][j][half * 2 + 0] * alpha;
                float v1 = acc[im][j][half * 2 + 1] * alpha;
                if (bias) { v0 += bias[gn]; v1 += bias[gn + 1]; }
                if (flags & FLAG_RELU) { v0 = fmaxf(v0, 0.f); v1 = fmaxf(v1, 0.f); }
                if (Rb) {
                    const float* rp = Rb + (long long)gm * ldres + gn;
                    v0 += rp[0]; v1 += rp[1];
                }
                float2 st; st.x = v0; st.y = v1;
                *reinterpret_cast<float2*>(Cb + (long long)gm * ldc + gn) = st;
            }
        }
    }
}

#define SMEM_BYTES(BN) (2 * 32 * ((128 + 8) + ((BN) + 8)) * 4)

static inline void gemm(const float* A, int lda, long long sAo, long long sAi,
                        const float* Bm, int ldb, long long sBo, long long sBi,
                        float* Cm, int ldc, long long sCo, long long sCi,
                        int M, int N, int K, int bOuter, int bInner,
                        float alpha, const float* bias,
                        const float* res, int ldres, long long sRo, long long sRi,
                        int flags) {
    dim3 grid(N / 128, M / 128, bOuter * bInner);
    mma_gemm<128, 2><<<grid, 256, SMEM_BYTES(128)>>>(
        A, lda, sAo, sAi, bInner, Bm, ldb, sBo, sBi, Cm, ldc, sCo, sCi,
        K, alpha, bias, res, ldres, sRo, sRi, flags);
}

// ================================ Launch ===================================
extern "C" void kernel_launch(void* const* d_in, const int* in_sizes, int n_in,
                              void* d_out, int out_size) {
    static int smem_cfg = 0;
    if (!smem_cfg) {
        cudaFuncSetAttribute((const void*)mma_gemm<128, 2>,
                             cudaFuncAttributeMaxDynamicSharedMemorySize, SMEM_BYTES(128));
        cudaFuncSetAttribute((const void*)fused_attn,
                             cudaFuncAttributeMaxDynamicSharedMemorySize, ATT_SMEM);
        smem_cfg = 1;
    }

    const float* x_T     = (const float*)d_in[0];
    const float* x_S     = (const float*)d_in[1];
    const float* Wq_t    = (const float*)d_in[2];
    const float* Wk_t    = (const float*)d_in[3];
    const float* Wv_t    = (const float*)d_in[4];
    const float* Wo      = (const float*)d_in[5];
    const float* Wq_s    = (const float*)d_in[6];
    const float* Wk_s    = (const float*)d_in[7];
    const float* ff1_w1  = (const float*)d_in[8];
    const float* ff1_b1  = (const float*)d_in[9];
    const float* ff1_w2  = (const float*)d_in[10];
    const float* ff1_b2  = (const float*)d_in[11];
    const float* ff2_w1  = (const float*)d_in[12];
    const float* ff2_b1  = (const float*)d_in[13];
    const float* ff2_w2  = (const float*)d_in[14];
    const float* ff2_b2  = (const float*)d_in[15];
    const float* t_ln1_w = (const float*)d_in[16];
    const float* t_ln1_b = (const float*)d_in[17];
    const float* t_ln2_w = (const float*)d_in[18];
    const float* t_ln2_b = (const float*)d_in[19];
    const float* s_ln1_w = (const float*)d_in[20];
    const float* s_ln1_b = (const float*)d_in[21];
    const float* fus_ln_w= (const float*)d_in[22];
    const float* fus_ln_b= (const float*)d_in[23];

    float* out = (float*)d_out;                 // [B,T,C]
    float* sw  = out + (size_t)N_BTC;           // [B,C,C]

    float* g = 0;
    cudaGetSymbolAddress((void**)&g, g_buf);
    float* h    = g + O_h;
    float* q    = g + O_q;
    float* k    = g + O_k;
    float* v    = g + O_v;
    float* ob   = g + O_o;
    float* xb   = g + O_x;
    float* h2   = g + O_h2;
    float* tout = g + O_tout;
    float* hs   = g + O_hs;
    float* qs   = g + O_qs;
    float* ks   = g + O_ks;
    float* x2b  = g + O_x2;
    float* h3   = g + O_h3;
    float* ffb  = g + O_ff;
    float* scS  = g + O_scS;

    const long long TC = (long long)T_ * C_;
    const long long CC = (long long)C_ * C_;

    // ---- temporal branch ----
    ln_kernel<<<B_ * T_, 256>>>(x_T, h, t_ln1_w, t_ln1_b, C_);

    gemm(h, C_, 0, 0, Wq_t, C_, 0, 0, q, C_, 0, 0, B_*T_, C_, C_, 1, 1,
         1.f, 0, 0, 0, 0, 0, FLAG_NT);
    gemm(h, C_, 0, 0, Wk_t, C_, 0, 0, k, C_, 0, 0, B_*T_, C_, C_, 1, 1,
         1.f, 0, 0, 0, 0, 0, FLAG_NT);
    gemm(h, C_, 0, 0, Wv_t, C_, 0, 0, v, C_, 0, 0, B_*T_, C_, C_, 1, 1,
         1.f, 0, 0, 0, 0, 0, FLAG_NT);

    // fused causal attention: q,k,v -> ob
    fused_attn<<<dim3(T_ / 128, B_ * H_), 256, ATT_SMEM>>>(q, k, v, ob);

    // x = x_T + ob @ Wo^T
    gemm(ob, C_, 0, 0, Wo, C_, 0, 0, xb, C_, 0, 0, B_*T_, C_, C_, 1, 1,
         1.f, 0, x_T, C_, 0, 0, FLAG_NT);

    ln_kernel<<<B_ * T_, 256>>>(xb, h2, t_ln2_w, t_ln2_b, C_);

    gemm(h2, C_, 0, 0, ff1_w1, C_, 0, 0, ffb, 4*C_, 0, 0, B_*T_, 4*C_, C_, 1, 1,
         1.f, ff1_b1, 0, 0, 0, 0, FLAG_NT | FLAG_RELU);
    gemm(ffb, 4*C_, 0, 0, ff1_w2, 4*C_, 0, 0, tout, C_, 0, 0, B_*T_, C_, 4*C_, 1, 1,
         1.f, ff1_b2, xb, C_, 0, 0, FLAG_NT);

    // ---- spatial branch ----
    ln_kernel<<<B_ * C_, 256>>>(x_S, hs, s_ln1_w, s_ln1_b, T_);

    gemm(hs, T_, 0, 0, Wq_s, T_, 0, 0, qs, T_, 0, 0, B_*C_, T_, T_, 1, 1,
         1.f, 0, 0, 0, 0, 0, FLAG_NT);
    gemm(hs, T_, 0, 0, Wk_s, T_, 0, 0, ks, T_, 0, 0, B_*C_, T_, T_, 1, 1,
         1.f, 0, 0, 0, 0, 0, FLAG_NT);

    gemm(qs, T_, (long long)C_*T_, HSS, ks, T_, (long long)C_*T_, HSS,
         scS, C_, (long long)H_*CC, CC,
         C_, C_, HSS, B_, H_,
         0.125f, 0, 0, 0, 0, 0, FLAG_NT);

    softmax_kernel<<<B_ * H_ * C_, 256>>>(scS, C_);
    mean_heads_kernel<<<(B_*C_*C_ + 255) / 256, 256>>>(scS, sw);

    // ---- fusion ----
    gemm(tout, C_, TC, 0, sw, C_, CC, 0,
         x2b, C_, TC, 0,
         T_, C_, C_, B_, 1,
         1.f, 0, tout, C_, TC, 0, FLAG_NT);

    ln_kernel<<<B_ * T_, 256>>>(x2b, h3, fus_ln_w, fus_ln_b, C_);

    gemm(h3, C_, 0, 0, ff2_w1, C_, 0, 0, ffb, 4*C_, 0, 0, B_*T_, 4*C_, C_, 1, 1,
         1.f, ff2_b1, 0, 0, 0, 0, FLAG_NT | FLAG_RELU);
    gemm(ffb, 4*C_, 0, 0, ff2_w2, 4*C_, 0, 0, out, C_, 0, 0, B_*T_, C_, 4*C_, 1, 1,
         1.f, ff2_b2, x2b, C_, 0, 0, FLAG_NT);
}

// round 13
// speedup vs baseline: 1.3625x; 1.3625x over previous
#include <cuda_runtime.h>
#include <cuda_bf16.h>
#include <math.h>

#define B_  16
#define T_  512
#define C_  256
#define H_  8
#define HST 32
#define HSS 64

#define N_BTC (B_*T_*C_)
#define N_FF  (B_*T_*4*C_)
#define N_SCT ((long long)B_*H_*T_*T_)
#define N_SCS ((long long)B_*H_*C_*C_)

#define O_h    0
#define O_q    (O_h    + N_BTC)
#define O_k    (O_q    + N_BTC)
#define O_v    (O_k    + N_BTC)
#define O_o    (O_v    + N_BTC)
#define O_x    (O_o    + N_BTC)
#define O_h2   (O_x    + N_BTC)
#define O_tout (O_h2   + N_BTC)
#define O_hs   (O_tout + N_BTC)
#define O_qs   (O_hs   + N_BTC)
#define O_ks   (O_qs   + N_BTC)
#define O_x2   (O_ks   + N_BTC)
#define O_h3   (O_x2   + N_BTC)
#define O_ff   (O_h3   + N_BTC)
#define O_scT  (O_ff   + N_FF)
#define O_scS  (O_scT  + N_SCT)
#define TOTAL_SCRATCH (O_scS + N_SCS)

__device__ float g_buf[TOTAL_SCRATCH];

// ============================== LayerNorm ==================================
__global__ void ln_kernel(const float* __restrict__ x, float* __restrict__ y,
                          const float* __restrict__ w, const float* __restrict__ b,
                          int L) {
    long long base = (long long)blockIdx.x * L;
    int tid = threadIdx.x;
    float s = 0.f, s2 = 0.f;
    for (int i = tid; i < L; i += 256) {
        float v = x[base + i];
        s += v; s2 += v * v;
    }
    __shared__ float sh[64];
    #pragma unroll
    for (int o = 16; o > 0; o >>= 1) {
        s  += __shfl_down_sync(0xffffffffu, s,  o);
        s2 += __shfl_down_sync(0xffffffffu, s2, o);
    }
    int warp = tid >> 5, lane = tid & 31;
    if (lane == 0) { sh[warp] = s; sh[warp + 32] = s2; }
    __syncthreads();
    if (tid == 0) {
        float ts = 0.f, ts2 = 0.f;
        for (int i = 0; i < 8; i++) { ts += sh[i]; ts2 += sh[32 + i]; }
        float m = ts / (float)L;
        float var = ts2 / (float)L - m * m;
        sh[0] = m;
        sh[1] = rsqrtf(var + 1e-6f);
    }
    __syncthreads();
    float m = sh[0], r = sh[1];
    for (int i = tid; i < L; i += 256)
        y[base + i] = (x[base + i] - m) * r * w[i] + b[i];
}

// ===================== Softmax (full row, length L<=512) ===================
__global__ void softmax_kernel(float* __restrict__ x, int L) {
    long long base = (long long)blockIdx.x * L;
    int tid = threadIdx.x;
    float v[2];
    #pragma unroll
    for (int c = 0; c < 2; c++) {
        int i = tid + c * 256;
        v[c] = (i < L) ? x[base + i] : -3.4e38f;
    }
    float mx = fmaxf(v[0], v[1]);
    __shared__ float sh[32];
    #pragma unroll
    for (int o = 16; o > 0; o >>= 1) mx = fmaxf(mx, __shfl_down_sync(0xffffffffu, mx, o));
    int warp = tid >> 5, lane = tid & 31;
    if (lane == 0) sh[warp] = mx;
    __syncthreads();
    if (tid == 0) {
        float m = sh[0];
        for (int i = 1; i < 8; i++) m = fmaxf(m, sh[i]);
        sh[0] = m;
    }
    __syncthreads();
    mx = sh[0];
    float sum = 0.f;
    #pragma unroll
    for (int c = 0; c < 2; c++) {
        int i = tid + c * 256;
        if (i < L) { v[c] = expf(v[c] - mx); sum += v[c]; }
    }
    __syncthreads();
    #pragma unroll
    for (int o = 16; o > 0; o >>= 1) sum += __shfl_down_sync(0xffffffffu, sum, o);
    if (lane == 0) sh[warp] = sum;
    __syncthreads();
    if (tid == 0) {
        float s = 0.f;
        for (int i = 0; i < 8; i++) s += sh[i];
        sh[0] = 1.f / s;
    }
    __syncthreads();
    float inv = sh[0];
    #pragma unroll
    for (int c = 0; c < 2; c++) {
        int i = tid + c * 256;
        if (i < L) x[base + i] = v[c] * inv;
    }
}

// ============== Causal softmax over rows of length T_ (=512) ===============
__global__ void softmax_causal_kernel(float* __restrict__ x) {
    long long base = (long long)blockIdx.x * T_;
    int t = blockIdx.x % T_;
    int tid = threadIdx.x;
    float v[2];
    bool act[2];
    #pragma unroll
    for (int c = 0; c < 2; c++) {
        int i = tid + c * 256;
        act[c] = (i <= t);
        v[c] = act[c] ? x[base + i] : -3.4e38f;
    }
    float mx = fmaxf(v[0], v[1]);
    __shared__ float sh[32];
    #pragma unroll
    for (int o = 16; o > 0; o >>= 1) mx = fmaxf(mx, __shfl_down_sync(0xffffffffu, mx, o));
    int warp = tid >> 5, lane = tid & 31;
    if (lane == 0) sh[warp] = mx;
    __syncthreads();
    if (tid == 0) {
        float m = sh[0];
        for (int i = 1; i < 8; i++) m = fmaxf(m, sh[i]);
        sh[0] = m;
    }
    __syncthreads();
    mx = sh[0];
    float sum = 0.f;
    #pragma unroll
    for (int c = 0; c < 2; c++) {
        if (act[c]) { v[c] = expf(v[c] - mx); sum += v[c]; }
    }
    __syncthreads();
    #pragma unroll
    for (int o = 16; o > 0; o >>= 1) sum += __shfl_down_sync(0xffffffffu, sum, o);
    if (lane == 0) sh[warp] = sum;
    __syncthreads();
    if (tid == 0) {
        float s = 0.f;
        for (int i = 0; i < 8; i++) s += sh[i];
        sh[0] = 1.f / s;
    }
    __syncthreads();
    float inv = sh[0];
    #pragma unroll
    for (int c = 0; c < 2; c++) {
        int i = tid + c * 256;
        x[base + i] = act[c] ? v[c] * inv : 0.f;
    }
}

// ============================ Mean over heads ==============================
__global__ void mean_heads_kernel(const float* __restrict__ sc, float* __restrict__ out) {
    long long idx = (long long)blockIdx.x * 256 + threadIdx.x;
    const long long NN = (long long)B_ * C_ * C_;
    if (idx >= NN) return;
    long long b = idx / (C_ * C_);
    long long r = idx % (C_ * C_);
    float s = 0.f;
    #pragma unroll
    for (int h = 0; h < H_; h++)
        s += sc[(b * H_ + h) * (long long)(C_ * C_) + r];
    out[idx] = s * 0.125f;
}

// ================= Pipelined tensor-core GEMM (3x BF16) ====================
#define FLAG_RELU    1
#define FLAG_NT      4
#define FLAG_TRISKIP 8
#define FLAG_KTRI    16

__device__ __forceinline__ void split2(float x0, float x1, unsigned &hi, unsigned &lo) {
    __nv_bfloat162 h = __floats2bfloat162_rn(x0, x1);
    float r0 = x0 - __bfloat162float(h.x);
    float r1 = x1 - __bfloat162float(h.y);
    __nv_bfloat162 l = __floats2bfloat162_rn(r0, r1);
    hi = *reinterpret_cast<unsigned*>(&h);
    lo = *reinterpret_cast<unsigned*>(&l);
}
__device__ __forceinline__ void mma16(float* c, const unsigned* a, const unsigned* b) {
    asm volatile("mma.sync.aligned.m16n8k16.row.col.f32.bf16.bf16.f32 "
        "{%0,%1,%2,%3}, {%4,%5,%6,%7}, {%8,%9}, {%0,%1,%2,%3};"
        : "+f"(c[0]), "+f"(c[1]), "+f"(c[2]), "+f"(c[3])
        : "r"(a[0]), "r"(a[1]), "r"(a[2]), "r"(a[3]), "r"(b[0]), "r"(b[1]));
}
// swizzle: column c of k-pair row kp stored at c ^ ((kp>>1 & 7)<<2)
__device__ __forceinline__ int SWZ(int kp, int c) { return c ^ (((kp >> 1) & 7) << 2); }

template<int BN, int WN>
__global__ __launch_bounds__(128 * WN)
void mma_gemm(const float* __restrict__ A, int lda, long long sAo, long long sAi, int nInner,
              const float* __restrict__ Bm, int ldb, long long sBo, long long sBi,
              float* __restrict__ Cm, int ldc, long long sCo, long long sCi,
              int K, float alpha,
              const float* __restrict__ bias,
              const float* __restrict__ res, int ldres, long long sRo, long long sRi,
              int flags) {
    constexpr int BM = 128, BK = 32;
    constexpr int THREADS = 128 * WN;
    constexpr int WNT = BN / WN;
    constexpr int NJ  = WNT / 8;
    constexpr int BMP = BM + 8, BNP = BN + 8;
    constexpr int AH_O = 0;
    constexpr int AL_O = 16 * BMP;
    constexpr int BH_O = 32 * BMP;
    constexpr int BL_O = 32 * BMP + 16 * BNP;
    constexpr int STG  = 32 * (BMP + BNP);
    constexpr int AITER = (BM * 8) / THREADS;
    constexpr int BITER = (BN * 8) / THREADS;

    if ((flags & FLAG_TRISKIP) && blockIdx.x > blockIdx.y) return;

    extern __shared__ unsigned sm[];

    int z  = blockIdx.z;
    int zo = z / nInner, zi = z % nInner;
    const float* Ab = A  + zo * sAo + zi * sAi;
    const float* Bb = Bm + zo * sBo + zi * sBi;
    float*       Cb = Cm + zo * sCo + zi * sCi;
    const float* Rb = res ? (res + zo * sRo + zi * sRi) : (const float*)0;

    int tid = threadIdx.x, lane = tid & 31, wid = tid >> 5;
    int wm = wid & 3, wn = wid >> 2;
    int row0 = blockIdx.y * BM;
    int col0 = blockIdx.x * BN;
    int r = lane >> 2, cq = lane & 3;
    bool nt = (flags & FLAG_NT) != 0;

    int Keff = (flags & FLAG_KTRI) ? min(K, row0 + BM) : K;
    int nk = Keff / BK;

    float4 ra[AITER], rb[BITER];

    auto loadT = [&](int k0) {
        #pragma unroll
        for (int i = 0; i < AITER; i++) {
            int idx = tid + i * THREADS;
            int m = idx >> 3, k4 = idx & 7;
            ra[i] = *reinterpret_cast<const float4*>(
                Ab + (long long)(row0 + m) * lda + k0 + k4 * 4);
        }
        if (nt) {
            #pragma unroll
            for (int i = 0; i < BITER; i++) {
                int idx = tid + i * THREADS;
                int n = idx >> 3, k4 = idx & 7;
                rb[i] = *reinterpret_cast<const float4*>(
                    Bb + (long long)(col0 + n) * ldb + k0 + k4 * 4);
            }
        } else {
            #pragma unroll
            for (int i = 0; i < BITER; i++) {
                #pragma unroll
                for (int pz = 0; pz < 2; pz++) {
                    int pidx = tid + (i * 2 + pz) * THREADS;
                    int kk2 = pidx / BN;
                    int n = pidx % BN;
                    const float* bp = Bb + (long long)(k0 + kk2 * 2) * ldb + col0 + n;
                    float b0 = bp[0], b1 = bp[ldb];
                    if (pz == 0) { rb[i].x = b0; rb[i].y = b1; }
                    else         { rb[i].z = b0; rb[i].w = b1; }
                }
            }
        }
    };

    auto storeT = [&](int s) {
        unsigned* ah = sm + s * STG + AH_O;
        unsigned* al = sm + s * STG + AL_O;
        unsigned* bh = sm + s * STG + BH_O;
        unsigned* bl = sm + s * STG + BL_O;
        #pragma unroll
        for (int i = 0; i < AITER; i++) {
            int idx = tid + i * THREADS;
            int m = idx >> 3, k4 = idx & 7;
            int mc = m ^ (k4 << 2);
            unsigned h0, l0, h1, l1;
            split2(ra[i].x, ra[i].y, h0, l0);
            split2(ra[i].z, ra[i].w, h1, l1);
            ah[(k4 * 2) * BMP + mc] = h0;     al[(k4 * 2) * BMP + mc] = l0;
            ah[(k4 * 2 + 1) * BMP + mc] = h1; al[(k4 * 2 + 1) * BMP + mc] = l1;
        }
        if (nt) {
            #pragma unroll
            for (int i = 0; i < BITER; i++) {
                int idx = tid + i * THREADS;
                int n = idx >> 3, k4 = idx & 7;
                int nc = n ^ (k4 << 2);
                unsigned h0, l0, h1, l1;
                split2(rb[i].x, rb[i].y, h0, l0);
                split2(rb[i].z, rb[i].w, h1, l1);
                bh[(k4 * 2) * BNP + nc] = h0;     bl[(k4 * 2) * BNP + nc] = l0;
                bh[(k4 * 2 + 1) * BNP + nc] = h1; bl[(k4 * 2 + 1) * BNP + nc] = l1;
            }
        } else {
            #pragma unroll
            for (int i = 0; i < BITER; i++) {
                #pragma unroll
                for (int pz = 0; pz < 2; pz++) {
                    int pidx = tid + (i * 2 + pz) * THREADS;
                    int kk2 = pidx / BN;
                    int n = pidx % BN;
                    int nc = SWZ(kk2, n);
                    float b0 = pz ? rb[i].z : rb[i].x;
                    float b1 = pz ? rb[i].w : rb[i].y;
                    unsigned h0, l0;
                    split2(b0, b1, h0, l0);
                    bh[kk2 * BNP + nc] = h0;
                    bl[kk2 * BNP + nc] = l0;
                }
            }
        }
    };

    float acc[2][NJ][4];
    #pragma unroll
    for (int i = 0; i < 2; i++)
        #pragma unroll
        for (int j = 0; j < NJ; j++)
            #pragma unroll
            for (int e = 0; e < 4; e++) acc[i][j][e] = 0.f;

    auto compute = [&](int s) {
        const unsigned* ah = sm + s * STG + AH_O;
        const unsigned* al = sm + s * STG + AL_O;
        const unsigned* bhp = sm + s * STG + BH_O;
        const unsigned* blp = sm + s * STG + BL_O;
        #pragma unroll
        for (int k16 = 0; k16 < 2; k16++) {
            int kp0 = k16 * 8 + cq, kp1 = kp0 + 4;
            unsigned bf_h[NJ][2], bf_l[NJ][2];
            #pragma unroll
            for (int j = 0; j < NJ; j++) {
                int ncol = wn * WNT + j * 8 + r;
                bf_h[j][0] = bhp[kp0 * BNP + SWZ(kp0, ncol)];
                bf_h[j][1] = bhp[kp1 * BNP + SWZ(kp1, ncol)];
                bf_l[j][0] = blp[kp0 * BNP + SWZ(kp0, ncol)];
                bf_l[j][1] = blp[kp1 * BNP + SWZ(kp1, ncol)];
            }
            #pragma unroll
            for (int im = 0; im < 2; im++) {
                int mrow = wm * 32 + im * 16 + r;
                unsigned afh[4], afl[4];
                afh[0] = ah[kp0 * BMP + SWZ(kp0, mrow)];
                afh[1] = ah[kp0 * BMP + SWZ(kp0, mrow + 8)];
                afh[2] = ah[kp1 * BMP + SWZ(kp1, mrow)];
                afh[3] = ah[kp1 * BMP + SWZ(kp1, mrow + 8)];
                afl[0] = al[kp0 * BMP + SWZ(kp0, mrow)];
                afl[1] = al[kp0 * BMP + SWZ(kp0, mrow + 8)];
                afl[2] = al[kp1 * BMP + SWZ(kp1, mrow)];
                afl[3] = al[kp1 * BMP + SWZ(kp1, mrow + 8)];
                #pragma unroll
                for (int j = 0; j < NJ; j++) {
                    mma16(acc[im][j], afl, bf_h[j]);
                    mma16(acc[im][j], afh, bf_l[j]);
                    mma16(acc[im][j], afh, bf_h[j]);
                }
            }
        }
    };

    // ---- pipelined mainloop: 1 sync per iteration, double-buffered ----
    loadT(0);
    storeT(0);
    int p = 0;
    for (int kb = 0; kb < nk; kb++) {
        __syncthreads();
        bool more = (kb + 1) < nk;
        if (more) loadT((kb + 1) * BK);
        compute(p);
        if (more) storeT(1 - p);
        p ^= 1;
    }

    // ---- epilogue ----
    #pragma unroll
    for (int im = 0; im < 2; im++) {
        #pragma unroll
        for (int j = 0; j < NJ; j++) {
            int gm0 = row0 + wm * 32 + im * 16 + r;
            int gn  = col0 + wn * WNT + j * 8 + cq * 2;
            #pragma unroll
            for (int half = 0; half < 2; half++) {
                int gm = gm0 + half * 8;
                float v0 = acc[im][j][half * 2 + 0] * alpha;
                float v1 = acc[im][j][half * 2 + 1] * alpha;
                if (bias) { v0 += bias[gn]; v1 += bias[gn + 1]; }
                if (flags & FLAG_RELU) { v0 = fmaxf(v0, 0.f); v1 = fmaxf(v1, 0.f); }
                if (Rb) {
                    const float* rp = Rb + (long long)gm * ldres + gn;
                    v0 += rp[0]; v1 += rp[1];
                }
                float2 st; st.x = v0; st.y = v1;
                *reinterpret_cast<float2*>(Cb + (long long)gm * ldc + gn) = st;
            }
        }
    }
}

#define SMEM_BYTES(BN) (2 * 32 * ((128 + 8) + ((BN) + 8)) * 4)

static inline void gemm(cudaStream_t st,
                        const float* A, int lda, long long sAo, long long sAi,
                        const float* Bm, int ldb, long long sBo, long long sBi,
                        float* Cm, int ldc, long long sCo, long long sCi,
                        int M, int N, int K, int bOuter, int bInner,
                        float alpha, const float* bias,
                        const float* res, int ldres, long long sRo, long long sRi,
                        int flags) {
    if (N == 32) {
        dim3 grid(1, M / 128, bOuter * bInner);
        mma_gemm<32, 1><<<grid, 128, SMEM_BYTES(32), st>>>(
            A, lda, sAo, sAi, bInner, Bm, ldb, sBo, sBi, Cm, ldc, sCo, sCi,
            K, alpha, bias, res, ldres, sRo, sRi, flags);
    } else {
        dim3 grid(N / 128, M / 128, bOuter * bInner);
        mma_gemm<128, 2><<<grid, 256, SMEM_BYTES(128), st>>>(
            A, lda, sAo, sAi, bInner, Bm, ldb, sBo, sBi, Cm, ldc, sCo, sCi,
            K, alpha, bias, res, ldres, sRo, sRi, flags);
    }
}

// ================================ Launch ===================================
extern "C" void kernel_launch(void* const* d_in, const int* in_sizes, int n_in,
                              void* d_out, int out_size) {
    static int cfg = 0;
    static cudaStream_t sSp, sV;          // spatial branch, v-projection
    static cudaEvent_t evStart, evLN, evV, evSp;
    if (!cfg) {
        cudaFuncSetAttribute((const void*)mma_gemm<128, 2>,
                             cudaFuncAttributeMaxDynamicSharedMemorySize, SMEM_BYTES(128));
        cudaFuncSetAttribute((const void*)mma_gemm<32, 1>,
                             cudaFuncAttributeMaxDynamicSharedMemorySize, SMEM_BYTES(32));
        cudaStreamCreateWithFlags(&sSp, cudaStreamNonBlocking);
        cudaStreamCreateWithFlags(&sV,  cudaStreamNonBlocking);
        cudaEventCreateWithFlags(&evStart, cudaEventDisableTiming);
        cudaEventCreateWithFlags(&evLN,    cudaEventDisableTiming);
        cudaEventCreateWithFlags(&evV,     cudaEventDisableTiming);
        cudaEventCreateWithFlags(&evSp,    cudaEventDisableTiming);
        cfg = 1;
    }

    const float* x_T     = (const float*)d_in[0];
    const float* x_S     = (const float*)d_in[1];
    const float* Wq_t    = (const float*)d_in[2];
    const float* Wk_t    = (const float*)d_in[3];
    const float* Wv_t    = (const float*)d_in[4];
    const float* Wo      = (const float*)d_in[5];
    const float* Wq_s    = (const float*)d_in[6];
    const float* Wk_s    = (const float*)d_in[7];
    const float* ff1_w1  = (const float*)d_in[8];
    const float* ff1_b1  = (const float*)d_in[9];
    const float* ff1_w2  = (const float*)d_in[10];
    const float* ff1_b2  = (const float*)d_in[11];
    const float* ff2_w1  = (const float*)d_in[12];
    const float* ff2_b1  = (const float*)d_in[13];
    const float* ff2_w2  = (const float*)d_in[14];
    const float* ff2_b2  = (const float*)d_in[15];
    const float* t_ln1_w = (const float*)d_in[16];
    const float* t_ln1_b = (const float*)d_in[17];
    const float* t_ln2_w = (const float*)d_in[18];
    const float* t_ln2_b = (const float*)d_in[19];
    const float* s_ln1_w = (const float*)d_in[20];
    const float* s_ln1_b = (const float*)d_in[21];
    const float* fus_ln_w= (const float*)d_in[22];
    const float* fus_ln_b= (const float*)d_in[23];

    float* out = (float*)d_out;                 // [B,T,C]
    float* sw  = out + (size_t)N_BTC;           // [B,C,C]

    float* g = 0;
    cudaGetSymbolAddress((void**)&g, g_buf);
    float* h    = g + O_h;
    float* q    = g + O_q;
    float* k    = g + O_k;
    float* v    = g + O_v;
    float* ob   = g + O_o;
    float* xb   = g + O_x;
    float* h2   = g + O_h2;
    float* tout = g + O_tout;
    float* hs   = g + O_hs;
    float* qs   = g + O_qs;
    float* ks   = g + O_ks;
    float* x2b  = g + O_x2;
    float* h3   = g + O_h3;
    float* ffb  = g + O_ff;
    float* scT  = g + O_scT;
    float* scS  = g + O_scS;

    const long long TC = (long long)T_ * C_;
    const long long TT = (long long)T_ * T_;
    const long long CC = (long long)C_ * C_;
    cudaStream_t s0 = 0;

    // ---- fork: spatial branch runs concurrently on sSp ----
    cudaEventRecord(evStart, s0);
    cudaStreamWaitEvent(sSp, evStart, 0);

    ln_kernel<<<B_ * C_, 256, 0, sSp>>>(x_S, hs, s_ln1_w, s_ln1_b, T_);
    gemm(sSp, hs, T_, 0, 0, Wq_s, T_, 0, 0, qs, T_, 0, 0, B_*C_, T_, T_, 1, 1,
         1.f, 0, 0, 0, 0, 0, FLAG_NT);
    gemm(sSp, hs, T_, 0, 0, Wk_s, T_, 0, 0, ks, T_, 0, 0, B_*C_, T_, T_, 1, 1,
         1.f, 0, 0, 0, 0, 0, FLAG_NT);
    gemm(sSp, qs, T_, (long long)C_*T_, HSS, ks, T_, (long long)C_*T_, HSS,
         scS, C_, (long long)H_*CC, CC,
         C_, C_, HSS, B_, H_,
         0.125f, 0, 0, 0, 0, 0, FLAG_NT);
    softmax_kernel<<<B_ * H_ * C_, 256, 0, sSp>>>(scS, C_);
    mean_heads_kernel<<<(B_*C_*C_ + 255) / 256, 256, 0, sSp>>>(scS, sw);
    cudaEventRecord(evSp, sSp);

    // ---- temporal branch on s0 ----
    ln_kernel<<<B_ * T_, 256, 0, s0>>>(x_T, h, t_ln1_w, t_ln1_b, C_);
    cudaEventRecord(evLN, s0);

    // v-projection overlaps scores+softmax on sV
    cudaStreamWaitEvent(sV, evLN, 0);
    gemm(sV, h, C_, 0, 0, Wv_t, C_, 0, 0, v, C_, 0, 0, B_*T_, C_, C_, 1, 1,
         1.f, 0, 0, 0, 0, 0, FLAG_NT);
    cudaEventRecord(evV, sV);

    gemm(s0, h, C_, 0, 0, Wq_t, C_, 0, 0, q, C_, 0, 0, B_*T_, C_, C_, 1, 1,
         1.f, 0, 0, 0, 0, 0, FLAG_NT);
    gemm(s0, h, C_, 0, 0, Wk_t, C_, 0, 0, k, C_, 0, 0, B_*T_, C_, C_, 1, 1,
         1.f, 0, 0, 0, 0, 0, FLAG_NT);

    gemm(s0, q, C_, TC, HST, k, C_, TC, HST,
         scT, T_, (long long)H_*TT, TT,
         T_, T_, HST, B_, H_,
         0.1767766952966369f, 0, 0, 0, 0, 0, FLAG_NT | FLAG_TRISKIP);

    softmax_causal_kernel<<<B_ * H_ * T_, 256, 0, s0>>>(scT);

    cudaStreamWaitEvent(s0, evV, 0);
    gemm(s0, scT, T_, (long long)H_*TT, TT, v, C_, TC, HST,
         ob, C_, TC, HST,
         T_, HST, T_, B_, H_,
         1.f, 0, 0, 0, 0, 0, FLAG_KTRI);

    gemm(s0, ob, C_, 0, 0, Wo, C_, 0, 0, xb, C_, 0, 0, B_*T_, C_, C_, 1, 1,
         1.f, 0, x_T, C_, 0, 0, FLAG_NT);

    ln_kernel<<<B_ * T_, 256, 0, s0>>>(xb, h2, t_ln2_w, t_ln2_b, C_);

    gemm(s0, h2, C_, 0, 0, ff1_w1, C_, 0, 0, ffb, 4*C_, 0, 0, B_*T_, 4*C_, C_, 1, 1,
         1.f, ff1_b1, 0, 0, 0, 0, FLAG_NT | FLAG_RELU);
    gemm(s0, ffb, 4*C_, 0, 0, ff1_w2, 4*C_, 0, 0, tout, C_, 0, 0, B_*T_, C_, 4*C_, 1, 1,
         1.f, ff1_b2, xb, C_, 0, 0, FLAG_NT);

    // ---- join: fusion needs spatial weights ----
    cudaStreamWaitEvent(s0, evSp, 0);
    gemm(s0, tout, C_, TC, 0, sw, C_, CC, 0,
         x2b, C_, TC, 0,
         T_, C_, C_, B_, 1,
         1.f, 0, tout, C_, TC, 0, FLAG_NT);

    ln_kernel<<<B_ * T_, 256, 0, s0>>>(x2b, h3, fus_ln_w, fus_ln_b, C_);

    gemm(s0, h3, C_, 0, 0, ff2_w1, C_, 0, 0, ffb, 4*C_, 0, 0, B_*T_, 4*C_, C_, 1, 1,
         1.f, ff2_b1, 0, 0, 0, 0, FLAG_NT | FLAG_RELU);
    gemm(s0, ffb, 4*C_, 0, 0, ff2_w2, 4*C_, 0, 0, out, C_, 0, 0, B_*T_, C_, 4*C_, 1, 1,
         1.f, ff2_b2, x2b, C_, 0, 0, FLAG_NT);
}